// round 1
// baseline (speedup 1.0000x reference)
#include <cuda_runtime.h>
#include <cstdint>

// ---------------- scratch (no allocations allowed; device globals) ----------------
__device__ float g_s1[1024 * 36 * 32 * 32];   // shared conv1 out (pooled)   151 MB
__device__ float g_s2[1024 * 36 * 16 * 16];   // shared conv2 out (pooled)    38 MB
__device__ float g_s3[1024 * 36 * 8 * 8];     // shared conv3 out (pooled)   9.4 MB
__device__ float g_p1[1024 * 12 * 32 * 32];   // private conv out (pooled)    50 MB
__device__ float g_x24[1024 * 24];            // concat [h | p]

// ---------------- fused conv3x3(SAME) + activation + maxpool2 ----------------
// Block = one image. Whole padded input image + all weights in SMEM.
// Each thread computes a 2x2 pooled tile = 4x4 conv pixels from a 6x6 patch.
// Padded row stride P = S+4 (multiple of 4) so patch rows load as aligned float4
// (conflict-free LDS.128; scalar loads would be 4-way bank conflicted).
template <int IC, int OC, int S, bool LEAKY, bool USE_DOM>
__global__ void convpool_kernel(const float* __restrict__ x,
                                const float* __restrict__ Wbase,
                                const float* __restrict__ Bbase,
                                const int* __restrict__ dom_ptr,
                                float* __restrict__ out)
{
    constexpr int PH = S + 2;     // padded rows
    constexpr int P  = S + 4;     // padded row stride (mult of 4)
    constexpr int HT = S / 4;     // 2x2-pooled tiles per dim
    constexpr int Sp = S / 2;     // pooled output dim
    extern __shared__ float smem[];
    float* sx = smem;                       // IC * PH * P
    float* sw = smem + IC * PH * P;         // OC * IC * 9

    const int b   = blockIdx.x;
    const int tid = threadIdx.x;
    const int nt  = blockDim.x;

    int dom = 0;
    if (USE_DOM) dom = dom_ptr[0];
    const float* W  = Wbase + (size_t)dom * OC * IC * 9;
    const float* Bv = Bbase + (size_t)dom * OC;

    for (int i = tid; i < IC * PH * P; i += nt) sx[i] = 0.f;
    __syncthreads();
    const float* xb = x + (size_t)b * IC * S * S;
    for (int i = tid; i < IC * S * S; i += nt) {
        int c  = i / (S * S);
        int r  = (i / S) % S;
        int cc = i % S;
        sx[c * PH * P + (r + 1) * P + (cc + 1)] = xb[i];
    }
    for (int i = tid; i < OC * IC * 9; i += nt) sw[i] = W[i];
    __syncthreads();

    constexpr int tilesPerOc = HT * HT;
    constexpr int tiles = OC * tilesPerOc;
    for (int t = tid; t < tiles; t += nt) {
        int oc  = t / tilesPerOc;
        int rem = t - oc * tilesPerOc;
        int ty  = rem / HT;
        int tx  = rem - ty * HT;

        float acc[16];
        #pragma unroll
        for (int i = 0; i < 16; i++) acc[i] = 0.f;

        const float* wp    = sw + oc * IC * 9;
        const float* xbase = sx + (4 * ty) * P + 4 * tx;

        for (int ci = 0; ci < IC; ci++) {
            const float* xp = xbase + ci * PH * P;
            float w0 = wp[0], w1 = wp[1], w2 = wp[2],
                  w3 = wp[3], w4 = wp[4], w5 = wp[5],
                  w6 = wp[6], w7 = wp[7], w8 = wp[8];
            wp += 9;
            float p[6][6];
            #pragma unroll
            for (int r = 0; r < 6; r++) {
                float4 a  = *reinterpret_cast<const float4*>(xp + r * P);
                float4 bq = *reinterpret_cast<const float4*>(xp + r * P + 4);
                p[r][0] = a.x;  p[r][1] = a.y;  p[r][2] = a.z;  p[r][3] = a.w;
                p[r][4] = bq.x; p[r][5] = bq.y;
            }
            #pragma unroll
            for (int r = 0; r < 4; r++) {
                #pragma unroll
                for (int c = 0; c < 4; c++) {
                    float s = acc[r * 4 + c];
                    s = fmaf(w0, p[r][c],         s);
                    s = fmaf(w1, p[r][c + 1],     s);
                    s = fmaf(w2, p[r][c + 2],     s);
                    s = fmaf(w3, p[r + 1][c],     s);
                    s = fmaf(w4, p[r + 1][c + 1], s);
                    s = fmaf(w5, p[r + 1][c + 2], s);
                    s = fmaf(w6, p[r + 2][c],     s);
                    s = fmaf(w7, p[r + 2][c + 1], s);
                    s = fmaf(w8, p[r + 2][c + 2], s);
                    acc[r * 4 + c] = s;
                }
            }
        }
        // act(max(conv)+b) == pool(act(conv+b)) for monotonic act
        float bias = Bv[oc];
        float* ob = out + (((size_t)b * OC + oc) * Sp + 2 * ty) * Sp + 2 * tx;
        #pragma unroll
        for (int pr = 0; pr < 2; pr++) {
            #pragma unroll
            for (int pc = 0; pc < 2; pc++) {
                float m = fmaxf(fmaxf(acc[(2*pr)*4 + 2*pc],   acc[(2*pr)*4 + 2*pc + 1]),
                                fmaxf(acc[(2*pr+1)*4 + 2*pc], acc[(2*pr+1)*4 + 2*pc + 1]));
                m += bias;
                float v;
                if (LEAKY) v = (m > 0.f) ? m : 0.001f * m;
                else       v = fmaxf(m, 0.f);
                ob[pr * Sp + pc] = v;
            }
        }
    }
}

// ---------------- FC: [B,K] @ W[12,K]^T + b -> write into concat buffer ----------------
// One warp per batch row; float4-vectorized K-strided dot + shuffle reduce.
template <int K, bool RELU, bool USE_DOM>
__global__ void fc12_kernel(const float* __restrict__ x,
                            const float* __restrict__ Wbase,
                            const float* __restrict__ Bbase,
                            const int* __restrict__ dom_ptr,
                            float* __restrict__ out, int out_off)
{
    const int warp = threadIdx.x >> 5;
    const int lane = threadIdx.x & 31;
    const int b = blockIdx.x * 8 + warp;
    int dom = 0;
    if (USE_DOM) dom = dom_ptr[0];
    const float* W = Wbase + (size_t)dom * 12 * K;
    const float4* xr = reinterpret_cast<const float4*>(x + (size_t)b * K);

    float4 acc[12];
    #pragma unroll
    for (int j = 0; j < 12; j++) acc[j] = make_float4(0.f, 0.f, 0.f, 0.f);

    for (int k4 = lane; k4 < K / 4; k4 += 32) {
        float4 xv = xr[k4];
        #pragma unroll
        for (int j = 0; j < 12; j++) {
            float4 wv = reinterpret_cast<const float4*>(W + (size_t)j * K)[k4];
            acc[j].x = fmaf(xv.x, wv.x, acc[j].x);
            acc[j].y = fmaf(xv.y, wv.y, acc[j].y);
            acc[j].z = fmaf(xv.z, wv.z, acc[j].z);
            acc[j].w = fmaf(xv.w, wv.w, acc[j].w);
        }
    }
    const float* Bv = Bbase + dom * 12;
    #pragma unroll
    for (int j = 0; j < 12; j++) {
        float s = (acc[j].x + acc[j].y) + (acc[j].z + acc[j].w);
        #pragma unroll
        for (int o = 16; o > 0; o >>= 1) s += __shfl_xor_sync(0xffffffffu, s, o);
        if (lane == j) {
            float v = s + Bv[j];
            if (RELU) v = fmaxf(v, 0.f);
            out[b * 24 + out_off + j] = v;
        }
    }
}

// ---------------- per-sample task-routed heads: 24 -> 28 -> 14 -> 5 ----------------
// One warp per sample; stages communicate via warp shuffles (no smem).
__global__ void heads_kernel(const float* __restrict__ x24,
                             const int* __restrict__ tt,
                             const float* __restrict__ W1, const float* __restrict__ b1,
                             const float* __restrict__ W2, const float* __restrict__ b2,
                             const float* __restrict__ W3, const float* __restrict__ b3,
                             float* __restrict__ out)
{
    const int warp = threadIdx.x >> 5;
    const int lane = threadIdx.x & 31;
    const int b = blockIdx.x * 8 + warp;
    const int t = tt[b];

    float xv = (lane < 24) ? x24[b * 24 + lane] : 0.f;

    const float* w1 = W1 + t * 28 * 24 + min(lane, 27) * 24;
    float h1 = 0.f;
    #pragma unroll
    for (int k = 0; k < 24; k++)
        h1 = fmaf(w1[k], __shfl_sync(0xffffffffu, xv, k), h1);
    if (lane < 28) h1 += b1[t * 28 + lane];
    h1 = fmaxf(h1, 0.f);
    if (lane >= 28) h1 = 0.f;

    const float* w2 = W2 + t * 14 * 28 + min(lane, 13) * 28;
    float h2 = 0.f;
    #pragma unroll
    for (int k = 0; k < 28; k++)
        h2 = fmaf(w2[k], __shfl_sync(0xffffffffu, h1, k), h2);
    if (lane < 14) h2 += b2[t * 14 + lane];
    h2 = fmaxf(h2, 0.f);
    if (lane >= 14) h2 = 0.f;

    const float* w3 = W3 + t * 5 * 14 + min(lane, 4) * 14;
    float o = 0.f;
    #pragma unroll
    for (int k = 0; k < 14; k++)
        o = fmaf(w3[k], __shfl_sync(0xffffffffu, h2, k), o);
    if (lane < 5) out[b * 5 + lane] = o + b3[t * 5 + lane];
}

// ---------------- launch ----------------
extern "C" void kernel_launch(void* const* d_in, const int* in_sizes, int n_in,
                              void* d_out, int out_size)
{
    const float* x_s = (const float*)d_in[0];
    const float* x_p = (const float*)d_in[1];
    const int*   tt  = (const int*)d_in[2];
    const int*   dom = (const int*)d_in[3];   // first 4 bytes hold value (int32/int64 LE)
    const float* WsW = (const float*)d_in[4];
    const float* Wsb = (const float*)d_in[5];
    const float* WhW = (const float*)d_in[6];
    const float* Whb = (const float*)d_in[7];
    const float* WfW = (const float*)d_in[8];
    const float* Wfb = (const float*)d_in[9];
    const float* PcW = (const float*)d_in[10];
    const float* Pcb = (const float*)d_in[11];
    const float* PlW = (const float*)d_in[12];
    const float* Plb = (const float*)d_in[13];
    const float* H1W = (const float*)d_in[14];
    const float* H1b = (const float*)d_in[15];
    const float* H2W = (const float*)d_in[16];
    const float* H2b = (const float*)d_in[17];
    const float* H3W = (const float*)d_in[18];
    const float* H3b = (const float*)d_in[19];
    float* out = (float*)d_out;
    const int B = in_sizes[2];  // 1024

    float *s1, *s2, *s3, *p1, *x24;
    cudaGetSymbolAddress((void**)&s1,  g_s1);
    cudaGetSymbolAddress((void**)&s2,  g_s2);
    cudaGetSymbolAddress((void**)&s3,  g_s3);
    cudaGetSymbolAddress((void**)&p1,  g_p1);
    cudaGetSymbolAddress((void**)&x24, g_x24);

    const size_t sm1 = (size_t)(3 * 66 * 68 + 36 * 3 * 9)   * sizeof(float); //  57.7 KB
    const size_t sm2 = (size_t)(36 * 34 * 36 + 36 * 36 * 9) * sizeof(float); // 222.9 KB
    const size_t sm3 = (size_t)(36 * 18 * 20 + 36 * 36 * 9) * sizeof(float); //  98.5 KB
    const size_t smp = (size_t)(3 * 66 * 68 + 12 * 3 * 9)   * sizeof(float); //  55.2 KB

    cudaFuncSetAttribute(convpool_kernel<3, 36, 64, false, false>,
                         cudaFuncAttributeMaxDynamicSharedMemorySize, (int)sm1);
    cudaFuncSetAttribute(convpool_kernel<36, 36, 32, false, false>,
                         cudaFuncAttributeMaxDynamicSharedMemorySize, (int)sm2);
    cudaFuncSetAttribute(convpool_kernel<36, 36, 16, false, false>,
                         cudaFuncAttributeMaxDynamicSharedMemorySize, (int)sm3);
    cudaFuncSetAttribute(convpool_kernel<3, 12, 64, true, true>,
                         cudaFuncAttributeMaxDynamicSharedMemorySize, (int)smp);

    // shared branch
    convpool_kernel<3, 36, 64, false, false><<<B, 256, sm1>>>(x_s, WsW, Wsb, nullptr, s1);
    convpool_kernel<36, 36, 32, false, false><<<B, 256, sm2>>>(s1, WhW, Whb, nullptr, s2);
    convpool_kernel<36, 36, 16, false, false><<<B, 256, sm3>>>(s2, WhW, Whb, nullptr, s3);
    // private branch
    convpool_kernel<3, 12, 64, true, true><<<B, 256, smp>>>(x_p, PcW, Pcb, dom, p1);
    // FCs -> concat buffer
    fc12_kernel<2304,  true,  false><<<B / 8, 256>>>(s3, WfW, Wfb, nullptr, x24, 0);
    fc12_kernel<12288, false, true ><<<B / 8, 256>>>(p1, PlW, Plb, dom,     x24, 12);
    // routed heads -> output
    heads_kernel<<<B / 8, 256>>>(x24, tt, H1W, H1b, H2W, H2b, H3W, H3b, out);
}